// round 11
// baseline (speedup 1.0000x reference)
#include <cuda_runtime.h>
#include <cuda_bf16.h>
#include <math_constants.h>
#include <cstdint>

// ---------------- problem constants (fixed shapes) ----------------
#define CDIM   256
#define HW     1024
#define NROWS  16384
#define KCODES 8192
#define NPART  1024

// ---------------- GEMM tiling ----------------
#define TILE_M 128
#define TILE_N 128
#define NTILES (KCODES / TILE_N)   // 64
#define CAP    128                 // candidate list capacity per row
#define MARGIN 2.0e-4f             // shortlist margin (dot units)
#define SA     264                 // padded smem row stride in bf16 (528B)
#define SAB    (SA * 2)            // bytes

// ---------------- device scratch (no allocations allowed) ----------------
__device__ float          g_S[NROWS];
__device__ int            g_idx[NROWS];
__device__ float          g_partial[NPART];
__device__ int            g_cnt[NROWS];
__device__ int            g_cand[NROWS * CAP];
__device__ __nv_bfloat16  g_A[NROWS * CDIM];
__device__ __nv_bfloat16  g_B[KCODES * CDIM];

// ---------------- helpers ----------------
__device__ __forceinline__ uint32_t smem_u32(const void* p) {
    uint32_t a;
    asm("{ .reg .u64 t; cvta.to.shared.u64 t, %1; cvt.u32.u64 %0, t; }" : "=r"(a) : "l"(p));
    return a;
}
__device__ __forceinline__ void cp16(uint32_t dst, const void* src) {
    asm volatile("cp.async.cg.shared.global [%0], [%1], 16;" :: "r"(dst), "l"(src));
}
__device__ __forceinline__ void cp_commit() { asm volatile("cp.async.commit_group;" ::: "memory"); }
__device__ __forceinline__ void cp_wait0()  { asm volatile("cp.async.wait_group 0;" ::: "memory"); }

__device__ __forceinline__ void mma_bf16(float& c0, float& c1, float& c2, float& c3,
                                         uint32_t a0, uint32_t a1, uint32_t a2, uint32_t a3,
                                         uint32_t b0, uint32_t b1) {
    asm volatile("mma.sync.aligned.m16n8k16.row.col.f32.bf16.bf16.f32 "
                 "{%0,%1,%2,%3}, {%4,%5,%6,%7}, {%8,%9}, {%0,%1,%2,%3};"
                 : "+f"(c0), "+f"(c1), "+f"(c2), "+f"(c3)
                 : "r"(a0), "r"(a1), "r"(a2), "r"(a3), "r"(b0), "r"(b1));
}
__device__ __forceinline__ void ldsm4(uint32_t& r0, uint32_t& r1, uint32_t& r2, uint32_t& r3,
                                      uint32_t addr) {
    asm volatile("ldmatrix.sync.aligned.m8n8.x4.shared.b16 {%0,%1,%2,%3}, [%4];"
                 : "=r"(r0), "=r"(r1), "=r"(r2), "=r"(r3) : "r"(addr));
}
// float atomic max on shared (handles mixed signs)
__device__ __forceinline__ void atomicMaxFloatS(float* addr, float value) {
    if (value >= 0.f) atomicMax((int*)addr, __float_as_int(value));
    else              atomicMin((unsigned int*)addr, __float_as_uint(value));
}

// ---------------------------------------------------------------------------
// Prep: A[n][c] = bf16(z[b,c,hw]) via smem transpose; B = bf16(emb); cnt=0
// ---------------------------------------------------------------------------
__global__ __launch_bounds__(1024) void vq_prep_z(const float* __restrict__ z) {
    __shared__ float t[32][33];
    int hw0 = blockIdx.x * 32, c0 = blockIdx.y * 32, b = blockIdx.z;
    const float* zp = z + ((size_t)b * CDIM + c0) * HW + hw0;
    t[threadIdx.y][threadIdx.x] = zp[(size_t)threadIdx.y * HW + threadIdx.x];
    __syncthreads();
    g_A[(size_t)(b * HW + hw0 + threadIdx.y) * CDIM + c0 + threadIdx.x] =
        __float2bfloat16(t[threadIdx.x][threadIdx.y]);
}
__global__ __launch_bounds__(256) void vq_prep_emb(const float* __restrict__ emb) {
    int t0 = blockIdx.x * 256 + threadIdx.x;
    for (int i = t0; i < KCODES * CDIM; i += gridDim.x * 256)
        g_B[i] = __float2bfloat16(emb[i]);
    if (t0 < NROWS) g_cnt[t0] = 0;
}

// ---------------------------------------------------------------------------
// S_n: sequential fp32 sum of z^2 in channel order (exact reference emulation)
// ---------------------------------------------------------------------------
__global__ __launch_bounds__(128) void vq_rownorm(const float* __restrict__ z) {
    int n = blockIdx.x * 128 + threadIdx.x;
    if (n >= NROWS) return;
    const float* p = z + (size_t)(n >> 10) * CDIM * HW + (n & (HW - 1));
    float s = 0.f;
    #pragma unroll 16
    for (int c = 0; c < CDIM; c++) {
        float v = p[(size_t)c * HW];
        s = __fadd_rn(s, __fmul_rn(v, v));
    }
    g_S[n] = s;
}

// ---------------------------------------------------------------------------
// bf16 HMMA GEMM + global-row-max margin shortlist.
// 1024 threads = 32 warps as 8(M) x 4(N); warp tile 16x32; block 128x128, K=256.
// A persistent in smem; B double-buffered (cp.async); ldmatrix.x4 fragments,
// fragment double-buffer inside unrolled k-loop. Per-row running max is held
// in smem and updated by all 4 stripe-warps (atomicMax) before appends.
// ---------------------------------------------------------------------------
__global__ __launch_bounds__(1024, 1) void vq_gemm(int dummy)
{
    extern __shared__ char smraw[];
    float* smax = (float*)smraw;                    // 128 floats (512B)
    __nv_bfloat16* Asm  = (__nv_bfloat16*)(smraw + 512);            // 128 x SA
    __nv_bfloat16* Bsm0 = (__nv_bfloat16*)(smraw + 512) + 128 * SA;
    __nv_bfloat16* Bsm1 = (__nv_bfloat16*)(smraw + 512) + 2 * 128 * SA;

    const int tid = threadIdx.x;
    const int wid = tid >> 5, lane = tid & 31;
    const int g = lane >> 2, t = lane & 3;
    const int wm = (wid & 7) * 16;                  // warp row base (8 M-groups)
    const int wn = (wid >> 3) * 32;                 // warp col base (4 N-stripes)
    const int n0 = blockIdx.x * TILE_M;

    const uint32_t sA  = smem_u32(Asm);
    const uint32_t sB0 = smem_u32(Bsm0);
    const uint32_t sB1 = smem_u32(Bsm1);

    // ldmatrix per-lane offsets (matrix m = lane>>3, row r = lane&7)
    const uint32_t aLOff = (uint32_t)(((((lane >> 3) & 1) * 8) + (lane & 7)) * SAB + (lane >> 4) * 16);
    const uint32_t bLOff = (uint32_t)(((lane >> 4) * 8 + (lane & 7)) * SAB + ((lane >> 3) & 1) * 16);

    if (tid < 128) smax[tid] = -CUDART_INF_F;

    // ---- prologue: persistent A tile + first B tile ----
    {
        const __nv_bfloat16* Ab = g_A + (size_t)n0 * CDIM;
        #pragma unroll
        for (int p = 0; p < 4; p++) {
            int i = tid + p * 1024;                 // 4096 16B chunks
            int row = i >> 5, cc = i & 31;
            cp16(sA + row * SAB + cc * 16, Ab + (size_t)row * CDIM + cc * 8);
        }
        const __nv_bfloat16* Bb = g_B;
        #pragma unroll
        for (int p = 0; p < 4; p++) {
            int i = tid + p * 1024;
            int row = i >> 5, cc = i & 31;
            cp16(sB0 + row * SAB + cc * 16, Bb + (size_t)row * CDIM + cc * 8);
        }
        cp_commit(); cp_wait0();
    }
    __syncthreads();

    int cur = 0;
    #pragma unroll 1
    for (int tt = 0; tt < NTILES; tt++) {
        // issue next B tile into the other buffer
        if (tt + 1 < NTILES) {
            const __nv_bfloat16* Bb = g_B + (size_t)(tt + 1) * TILE_N * CDIM;
            uint32_t dst = cur ? sB0 : sB1;
            #pragma unroll
            for (int p = 0; p < 4; p++) {
                int i = tid + p * 1024;
                int row = i >> 5, cc = i & 31;
                cp16(dst + row * SAB + cc * 16, Bb + (size_t)row * CDIM + cc * 8);
            }
        }
        cp_commit();

        const uint32_t sB = cur ? sB1 : sB0;

        float C[4][4];                              // [nf][quad]
        #pragma unroll
        for (int nf = 0; nf < 4; nf++)
            #pragma unroll
            for (int q = 0; q < 4; q++) C[nf][q] = 0.f;

        uint32_t aF[2][4], bF[2][4][2];
        ldsm4(aF[0][0], aF[0][1], aF[0][2], aF[0][3], sA + wm * SAB + aLOff);
        #pragma unroll
        for (int p = 0; p < 2; p++)
            ldsm4(bF[0][2 * p][0], bF[0][2 * p][1], bF[0][2 * p + 1][0], bF[0][2 * p + 1][1],
                  sB + (wn + p * 16) * SAB + bLOff);

        #pragma unroll
        for (int ks = 0; ks < 16; ks++) {
            const int cb = ks & 1;
            if (ks < 15) {
                const int nb = cb ^ 1;
                const uint32_t koff = (uint32_t)((ks + 1) * 32);
                ldsm4(aF[nb][0], aF[nb][1], aF[nb][2], aF[nb][3],
                      sA + wm * SAB + koff + aLOff);
                #pragma unroll
                for (int p = 0; p < 2; p++)
                    ldsm4(bF[nb][2 * p][0], bF[nb][2 * p][1], bF[nb][2 * p + 1][0], bF[nb][2 * p + 1][1],
                          sB + (wn + p * 16) * SAB + koff + bLOff);
            }
            #pragma unroll
            for (int nf = 0; nf < 4; nf++)
                mma_bf16(C[nf][0], C[nf][1], C[nf][2], C[nf][3],
                         aF[cb][0], aF[cb][1], aF[cb][2], aF[cb][3],
                         bF[cb][nf][0], bF[cb][nf][1]);
        }

        // ---- epilogue phase 1: contribute stripe max to global row max ----
        #pragma unroll
        for (int h = 0; h < 2; h++) {
            float lm = -CUDART_INF_F;
            #pragma unroll
            for (int nf = 0; nf < 4; nf++)
                lm = fmaxf(lm, fmaxf(C[nf][2 * h], C[nf][2 * h + 1]));
            lm = fmaxf(lm, __shfl_xor_sync(0xffffffffu, lm, 1));
            lm = fmaxf(lm, __shfl_xor_sync(0xffffffffu, lm, 2));
            if (t == 0) atomicMaxFloatS(&smax[wm + g + h * 8], lm);
        }
        __syncthreads();
        // ---- epilogue phase 2: append candidates vs global row threshold ----
        #pragma unroll
        for (int h = 0; h < 2; h++) {
            const int rowl = wm + g + h * 8;
            const float thr = smax[rowl] - MARGIN;
            const int rowg = n0 + rowl;
            #pragma unroll
            for (int nf = 0; nf < 4; nf++) {
                #pragma unroll
                for (int p = 0; p < 2; p++) {
                    float s = C[nf][2 * h + p];
                    if (s >= thr) {
                        int col = tt * TILE_N + wn + nf * 8 + 2 * t + p;
                        int pos = atomicAdd(&g_cnt[rowg], 1);
                        if (pos < CAP) g_cand[rowg * CAP + pos] = col;
                    }
                }
            }
        }

        cp_wait0();
        __syncthreads();
        cur ^= 1;
    }
}

// ---------------------------------------------------------------------------
// Exact fp32 re-rank: one warp per row, ascending-c fma chain (bit-exact
// with the R3-passing recurrence). Lexicographic (d, idx) min.
// ---------------------------------------------------------------------------
__global__ __launch_bounds__(256) void vq_rerank(
    const float* __restrict__ z, const float* __restrict__ emb)
{
    const int w = threadIdx.x >> 5, lane = threadIdx.x & 31;
    const int n = blockIdx.x * 8 + w;
    if (n >= NROWS) return;
    const float* zp = z + (size_t)(n >> 10) * CDIM * HW + (n & (HW - 1));
    const float S = g_S[n];
    const int cnt = g_cnt[n];

    float bestd = CUDART_INF_F;
    int   besti = 0x7fffffff;

    if (cnt <= CAP) {
        for (int base = 0; base < cnt; base += 32) {
            int q = base + lane;
            float d = CUDART_INF_F; int k = 0x7fffffff;
            if (q < cnt) {
                k = g_cand[n * CAP + q];
                const float* ep = emb + (size_t)k * CDIM;
                float acc = 0.f;
                #pragma unroll 8
                for (int c = 0; c < CDIM; c++)
                    acc = fmaf(zp[(size_t)c * HW], ep[c], acc);
                d = __fadd_rn(S, -2.0f * acc);
            }
            if (d < bestd || (d == bestd && k < besti)) { bestd = d; besti = k; }
        }
    } else {
        // correctness net (should be unreachable with global-row-max threshold)
        for (int k = lane; k < KCODES; k += 32) {
            const float* ep = emb + (size_t)k * CDIM;
            float acc = 0.f;
            #pragma unroll 8
            for (int c = 0; c < CDIM; c++)
                acc = fmaf(zp[(size_t)c * HW], ep[c], acc);
            float d = __fadd_rn(S, -2.0f * acc);
            if (d < bestd || (d == bestd && k < besti)) { bestd = d; besti = k; }
        }
    }
    #pragma unroll
    for (int off = 16; off >= 1; off >>= 1) {
        float od = __shfl_xor_sync(0xffffffffu, bestd, off);
        int   oi = __shfl_xor_sync(0xffffffffu, besti, off);
        if (od < bestd || (od == bestd && oi < besti)) { bestd = od; besti = oi; }
    }
    if (lane == 0) g_idx[n] = besti;
}

// ---------------------------------------------------------------------------
// Gather + straight-through output + loss partials (R3-exact)
// ---------------------------------------------------------------------------
__global__ __launch_bounds__(256) void vq_gather(
    const float* __restrict__ z, const float* __restrict__ emb,
    float* __restrict__ out, int total)
{
    __shared__ float red[256];
    float local = 0.f;
    const int stride = gridDim.x * blockDim.x;
    for (int e = blockIdx.x * blockDim.x + threadIdx.x; e < total; e += stride) {
        int hw = e & (HW - 1);
        int c  = (e >> 10) & (CDIM - 1);
        int bb = e >> 18;
        int id = g_idx[bb * HW + hw];
        float q  = emb[(size_t)id * CDIM + c];
        float zv = z[e];
        float d  = __fadd_rn(q, -zv);
        out[e] = __fadd_rn(zv, d);
        local = fmaf(d, d, local);
    }
    red[threadIdx.x] = local;
    __syncthreads();
    #pragma unroll
    for (int s = 128; s >= 1; s >>= 1) {
        if (threadIdx.x < s) red[threadIdx.x] += red[threadIdx.x + s];
        __syncthreads();
    }
    if (threadIdx.x == 0) g_partial[blockIdx.x] = red[0];
}

// Finalize: block 0 reduces loss; all blocks write indices-as-float tail.
__global__ __launch_bounds__(256) void vq_final(float* __restrict__ out, int total, int rows) {
    if (blockIdx.x == 0) {
        __shared__ double dred[256];
        double s = 0.0;
        for (int i = threadIdx.x; i < NPART; i += 256) s += (double)g_partial[i];
        dred[threadIdx.x] = s;
        __syncthreads();
        #pragma unroll
        for (int st = 128; st >= 1; st >>= 1) {
            if (threadIdx.x < st) dred[threadIdx.x] += dred[threadIdx.x + st];
            __syncthreads();
        }
        if (threadIdx.x == 0) {
            double loss = dred[0] / (double)total;
            out[total]     = (float)loss;
            out[total + 1] = (float)(0.25 * loss);
        }
    }
    int i = blockIdx.x * 256 + threadIdx.x;
    if (i < rows) out[total + 2 + i] = (float)g_idx[i];
}

// ---------------------------------------------------------------------------
extern "C" void kernel_launch(void* const* d_in, const int* in_sizes, int n_in,
                              void* d_out, int out_size)
{
    const float* z   = (const float*)d_in[0];   // [16,256,32,32]
    const float* emb = (const float*)d_in[1];   // [8192,256]
    float* out = (float*)d_out;
    const int z_total = in_sizes[0];            // 4194304
    const int rows = z_total / CDIM;            // 16384

    const int SM_TOTAL = 512 + 3 * 128 * SA * 2;  // 203264 B
    cudaFuncSetAttribute(vq_gemm, cudaFuncAttributeMaxDynamicSharedMemorySize, SM_TOTAL);

    vq_prep_z<<<dim3(HW / 32, CDIM / 32, 16), dim3(32, 32)>>>(z);
    vq_prep_emb<<<512, 256>>>(emb);
    vq_rownorm<<<(rows + 127) / 128, 128>>>(z);
    vq_gemm<<<rows / TILE_M, 1024, SM_TOTAL>>>(0);
    vq_rerank<<<(rows + 7) / 8, 256>>>(z, emb);
    vq_gather<<<NPART, 256>>>(z, emb, out, z_total);
    if (out_size >= z_total + 2 + rows)
        vq_final<<<(rows + 255) / 256, 256>>>(out, z_total, rows);
}

// round 12
// speedup vs baseline: 1.0171x; 1.0171x over previous
#include <cuda_runtime.h>
#include <cuda_bf16.h>
#include <math_constants.h>
#include <cstdint>

// ---------------- problem constants (fixed shapes) ----------------
#define CDIM   256
#define HW     1024
#define NROWS  16384
#define KCODES 8192
#define NPART  4096

// ---------------- GEMM tiling ----------------
#define TILE_M 128
#define TILE_N 128
#define NTILES (KCODES / TILE_N)   // 64
#define CAP    128                 // candidate list capacity per row
#define MARGIN 2.0e-4f             // shortlist margin (dot units)
#define SA     264                 // padded smem row stride in bf16 (528B)
#define SAB    (SA * 2)            // bytes

// ---------------- device scratch (no allocations allowed) ----------------
__device__ float          g_S[NROWS];
__device__ int            g_idx[NROWS];
__device__ float          g_partial[NPART];
__device__ int            g_cand[NROWS * CAP];
__device__ __nv_bfloat16  g_A[NROWS * CDIM];
__device__ __nv_bfloat16  g_B[KCODES * CDIM];

// ---------------- helpers ----------------
__device__ __forceinline__ uint32_t smem_u32(const void* p) {
    uint32_t a;
    asm("{ .reg .u64 t; cvta.to.shared.u64 t, %1; cvt.u32.u64 %0, t; }" : "=r"(a) : "l"(p));
    return a;
}
__device__ __forceinline__ void cp16(uint32_t dst, const void* src) {
    asm volatile("cp.async.cg.shared.global [%0], [%1], 16;" :: "r"(dst), "l"(src));
}
__device__ __forceinline__ void cp_commit() { asm volatile("cp.async.commit_group;" ::: "memory"); }
__device__ __forceinline__ void cp_wait0()  { asm volatile("cp.async.wait_group 0;" ::: "memory"); }

__device__ __forceinline__ void mma_bf16(float& c0, float& c1, float& c2, float& c3,
                                         uint32_t a0, uint32_t a1, uint32_t a2, uint32_t a3,
                                         uint32_t b0, uint32_t b1) {
    asm volatile("mma.sync.aligned.m16n8k16.row.col.f32.bf16.bf16.f32 "
                 "{%0,%1,%2,%3}, {%4,%5,%6,%7}, {%8,%9}, {%0,%1,%2,%3};"
                 : "+f"(c0), "+f"(c1), "+f"(c2), "+f"(c3)
                 : "r"(a0), "r"(a1), "r"(a2), "r"(a3), "r"(b0), "r"(b1));
}
__device__ __forceinline__ void ldsm4(uint32_t& r0, uint32_t& r1, uint32_t& r2, uint32_t& r3,
                                      uint32_t addr) {
    asm volatile("ldmatrix.sync.aligned.m8n8.x4.shared.b16 {%0,%1,%2,%3}, [%4];"
                 : "=r"(r0), "=r"(r1), "=r"(r2), "=r"(r3) : "r"(addr));
}
// float atomic max on shared (handles mixed signs)
__device__ __forceinline__ void atomicMaxFloatS(float* addr, float value) {
    if (value >= 0.f) atomicMax((int*)addr, __float_as_int(value));
    else              atomicMin((unsigned int*)addr, __float_as_uint(value));
}

// ---------------------------------------------------------------------------
// Prep: A[n][c] = bf16(z[b,c,hw]) via smem transpose; B = bf16(emb)
// ---------------------------------------------------------------------------
__global__ __launch_bounds__(1024) void vq_prep_z(const float* __restrict__ z) {
    __shared__ float t[32][33];
    int hw0 = blockIdx.x * 32, c0 = blockIdx.y * 32, b = blockIdx.z;
    const float* zp = z + ((size_t)b * CDIM + c0) * HW + hw0;
    t[threadIdx.y][threadIdx.x] = zp[(size_t)threadIdx.y * HW + threadIdx.x];
    __syncthreads();
    g_A[(size_t)(b * HW + hw0 + threadIdx.y) * CDIM + c0 + threadIdx.x] =
        __float2bfloat16(t[threadIdx.x][threadIdx.y]);
}
__global__ __launch_bounds__(256) void vq_prep_emb(const float* __restrict__ emb) {
    int t0 = blockIdx.x * 256 + threadIdx.x;
    for (int i = t0; i < KCODES * CDIM; i += gridDim.x * 256)
        g_B[i] = __float2bfloat16(emb[i]);
}

// ---------------------------------------------------------------------------
// S_n: sequential fp32 sum of z^2 in channel order (exact reference emulation)
// ---------------------------------------------------------------------------
__global__ __launch_bounds__(128) void vq_rownorm(const float* __restrict__ z) {
    int n = blockIdx.x * 128 + threadIdx.x;
    if (n >= NROWS) return;
    const float* p = z + (size_t)(n >> 10) * CDIM * HW + (n & (HW - 1));
    float s = 0.f;
    #pragma unroll 16
    for (int c = 0; c < CDIM; c++) {
        float v = p[(size_t)c * HW];
        s = __fadd_rn(s, __fmul_rn(v, v));
    }
    g_S[n] = s;
}

// ---------------------------------------------------------------------------
// bf16 HMMA GEMM + global-row-max margin shortlist + FUSED exact re-rank.
// 512 threads = 16 warps as 4(M) x 4(N); warp tile 32x32; block 128x128, K=256.
// A persistent in smem; B double-buffered (cp.async); ldmatrix.x4 fragments,
// fragment double-buffer inside unrolled k-loop. Per-row running max + append
// counters in smem. After the tile loop the CTA reranks its own 128 rows with
// the exact fp32 recurrence (bit-identical to the R3-passing kernel).
// ---------------------------------------------------------------------------
__global__ __launch_bounds__(512, 1) void vq_gemm(
    const float* __restrict__ z, const float* __restrict__ emb)
{
    extern __shared__ char smraw[];
    float* smax = (float*)smraw;                    // 128 floats
    int*   scnt = (int*)(smraw + 512);              // 128 ints
    __nv_bfloat16* Asm  = (__nv_bfloat16*)(smraw + 1024);           // 128 x SA
    __nv_bfloat16* Bsm0 = (__nv_bfloat16*)(smraw + 1024) + 128 * SA;
    __nv_bfloat16* Bsm1 = (__nv_bfloat16*)(smraw + 1024) + 2 * 128 * SA;

    const int tid = threadIdx.x;
    const int wid = tid >> 5, lane = tid & 31;
    const int g = lane >> 2, t = lane & 3;
    const int wm = (wid >> 2) * 32;                 // warp row base
    const int wn = (wid & 3) * 32;                  // warp col base
    const int n0 = blockIdx.x * TILE_M;

    const uint32_t sA  = smem_u32(Asm);
    const uint32_t sB0 = smem_u32(Bsm0);
    const uint32_t sB1 = smem_u32(Bsm1);

    // ldmatrix per-lane offsets (matrix m = lane>>3, row r = lane&7)
    const uint32_t aLOff = (uint32_t)(((((lane >> 3) & 1) * 8) + (lane & 7)) * SAB + (lane >> 4) * 16);
    const uint32_t bLOff = (uint32_t)(((lane >> 4) * 8 + (lane & 7)) * SAB + ((lane >> 3) & 1) * 16);

    if (tid < 128) { smax[tid] = -CUDART_INF_F; scnt[tid] = 0; }

    // ---- prologue: persistent A tile + first B tile ----
    {
        const __nv_bfloat16* Ab = g_A + (size_t)n0 * CDIM;
        #pragma unroll
        for (int p = 0; p < 8; p++) {
            int i = tid + p * 512;                  // 4096 16B chunks
            int row = i >> 5, cc = i & 31;
            cp16(sA + row * SAB + cc * 16, Ab + (size_t)row * CDIM + cc * 8);
        }
        const __nv_bfloat16* Bb = g_B;
        #pragma unroll
        for (int p = 0; p < 8; p++) {
            int i = tid + p * 512;
            int row = i >> 5, cc = i & 31;
            cp16(sB0 + row * SAB + cc * 16, Bb + (size_t)row * CDIM + cc * 8);
        }
        cp_commit(); cp_wait0();
    }
    __syncthreads();

    int cur = 0;
    #pragma unroll 1
    for (int tt = 0; tt < NTILES; tt++) {
        // issue next B tile into the other buffer
        if (tt + 1 < NTILES) {
            const __nv_bfloat16* Bb = g_B + (size_t)(tt + 1) * TILE_N * CDIM;
            uint32_t dst = cur ? sB0 : sB1;
            #pragma unroll
            for (int p = 0; p < 8; p++) {
                int i = tid + p * 512;
                int row = i >> 5, cc = i & 31;
                cp16(dst + row * SAB + cc * 16, Bb + (size_t)row * CDIM + cc * 8);
            }
        }
        cp_commit();

        const uint32_t sB = cur ? sB1 : sB0;

        float C[2][4][4];
        #pragma unroll
        for (int mf = 0; mf < 2; mf++)
            #pragma unroll
            for (int nf = 0; nf < 4; nf++)
                #pragma unroll
                for (int q = 0; q < 4; q++) C[mf][nf][q] = 0.f;

        uint32_t aF[2][2][4], bF[2][4][2];
        #pragma unroll
        for (int mf = 0; mf < 2; mf++)
            ldsm4(aF[0][mf][0], aF[0][mf][1], aF[0][mf][2], aF[0][mf][3],
                  sA + (wm + mf * 16) * SAB + aLOff);
        #pragma unroll
        for (int p = 0; p < 2; p++)
            ldsm4(bF[0][2 * p][0], bF[0][2 * p][1], bF[0][2 * p + 1][0], bF[0][2 * p + 1][1],
                  sB + (wn + p * 16) * SAB + bLOff);

        #pragma unroll
        for (int ks = 0; ks < 16; ks++) {
            const int cb = ks & 1;
            if (ks < 15) {
                const int nb = cb ^ 1;
                const uint32_t koff = (uint32_t)((ks + 1) * 32);
                #pragma unroll
                for (int mf = 0; mf < 2; mf++)
                    ldsm4(aF[nb][mf][0], aF[nb][mf][1], aF[nb][mf][2], aF[nb][mf][3],
                          sA + (wm + mf * 16) * SAB + koff + aLOff);
                #pragma unroll
                for (int p = 0; p < 2; p++)
                    ldsm4(bF[nb][2 * p][0], bF[nb][2 * p][1], bF[nb][2 * p + 1][0], bF[nb][2 * p + 1][1],
                          sB + (wn + p * 16) * SAB + koff + bLOff);
            }
            #pragma unroll
            for (int mf = 0; mf < 2; mf++)
                #pragma unroll
                for (int nf = 0; nf < 4; nf++)
                    mma_bf16(C[mf][nf][0], C[mf][nf][1], C[mf][nf][2], C[mf][nf][3],
                             aF[cb][mf][0], aF[cb][mf][1], aF[cb][mf][2], aF[cb][mf][3],
                             bF[cb][nf][0], bF[cb][nf][1]);
        }

        // ---- epilogue phase 1: contribute stripe max to global row max ----
        #pragma unroll
        for (int mf = 0; mf < 2; mf++) {
            #pragma unroll
            for (int h = 0; h < 2; h++) {
                float lm = -CUDART_INF_F;
                #pragma unroll
                for (int nf = 0; nf < 4; nf++)
                    lm = fmaxf(lm, fmaxf(C[mf][nf][2 * h], C[mf][nf][2 * h + 1]));
                lm = fmaxf(lm, __shfl_xor_sync(0xffffffffu, lm, 1));
                lm = fmaxf(lm, __shfl_xor_sync(0xffffffffu, lm, 2));
                if (t == 0) atomicMaxFloatS(&smax[wm + mf * 16 + g + h * 8], lm);
            }
        }
        __syncthreads();
        // ---- epilogue phase 2: append candidates vs global row threshold ----
        #pragma unroll
        for (int mf = 0; mf < 2; mf++) {
            #pragma unroll
            for (int h = 0; h < 2; h++) {
                const int rowl = wm + mf * 16 + g + h * 8;
                const float thr = smax[rowl] - MARGIN;
                const int rowg = n0 + rowl;
                #pragma unroll
                for (int nf = 0; nf < 4; nf++) {
                    #pragma unroll
                    for (int p = 0; p < 2; p++) {
                        float s = C[mf][nf][2 * h + p];
                        if (s >= thr) {
                            int col = tt * TILE_N + wn + nf * 8 + 2 * t + p;
                            int pos = atomicAdd(&scnt[rowl], 1);
                            if (pos < CAP) g_cand[rowg * CAP + pos] = col;
                        }
                    }
                }
            }
        }

        cp_wait0();
        __syncthreads();
        cur ^= 1;
    }

    // ---- fused exact fp32 re-rank: 4 threads per row, this CTA's 128 rows ----
    {
        const int row = tid >> 2, sub = tid & 3;
        const int n = n0 + row;
        const float* zp = z + (size_t)(n >> 10) * CDIM * HW + (n & (HW - 1));
        const float S = g_S[n];
        const int cnt = scnt[row];

        float bestd = CUDART_INF_F;
        int   besti = 0x7fffffff;

        if (cnt <= CAP) {
            for (int q = sub; q < cnt; q += 4) {
                int k = g_cand[n * CAP + q];
                const float* ep = emb + (size_t)k * CDIM;
                float acc = 0.f;
                #pragma unroll 8
                for (int c = 0; c < CDIM; c++)
                    acc = fmaf(zp[(size_t)c * HW], ep[c], acc);
                float d = __fadd_rn(S, -2.0f * acc);
                if (d < bestd || (d == bestd && k < besti)) { bestd = d; besti = k; }
            }
        } else {
            // correctness net (unreachable with global-row-max threshold)
            for (int k = sub; k < KCODES; k += 4) {
                const float* ep = emb + (size_t)k * CDIM;
                float acc = 0.f;
                #pragma unroll 8
                for (int c = 0; c < CDIM; c++)
                    acc = fmaf(zp[(size_t)c * HW], ep[c], acc);
                float d = __fadd_rn(S, -2.0f * acc);
                if (d < bestd || (d == bestd && k < besti)) { bestd = d; besti = k; }
            }
        }
        #pragma unroll
        for (int off = 1; off <= 2; off <<= 1) {
            float od = __shfl_xor_sync(0xffffffffu, bestd, off);
            int   oi = __shfl_xor_sync(0xffffffffu, besti, off);
            if (od < bestd || (od == bestd && oi < besti)) { bestd = od; besti = oi; }
        }
        if (sub == 0) g_idx[n] = besti;
    }
}

// ---------------------------------------------------------------------------
// Coalesced gather: 32x32 (hw x c) patches via smem transpose.
// emb rows loaded coalesced per hw position; output written coalesced.
// Rounding identical to reference: d = fl(q - z); out = fl(z + d).
// ---------------------------------------------------------------------------
__global__ __launch_bounds__(1024) void vq_gather(
    const float* __restrict__ z, const float* __restrict__ emb,
    float* __restrict__ out)
{
    __shared__ float eT[32][33];
    __shared__ int   ids[32];
    __shared__ float red[32];

    const int tx = threadIdx.x, ty = threadIdx.y;
    const int tid = ty * 32 + tx;
    const int hw0 = blockIdx.x * 32, c0 = blockIdx.y * 32, b = blockIdx.z;

    if (tid < 32) ids[tid] = g_idx[b * HW + hw0 + tid];
    __syncthreads();

    // warp ty loads emb row for hw position (hw0+ty), columns c0+tx  (coalesced)
    eT[ty][tx] = emb[(size_t)ids[ty] * CDIM + c0 + tx];
    __syncthreads();

    // element (c = c0+ty, hw = hw0+tx): emb value = eT[tx][ty]
    const size_t e = (size_t)b * (CDIM * HW) + (size_t)(c0 + ty) * HW + hw0 + tx;
    float zv = z[e];
    float q  = eT[tx][ty];
    float d  = __fadd_rn(q, -zv);
    out[e] = __fadd_rn(zv, d);
    float local = d * d;

    // block reduction (deterministic): warp shuffle + smem
    #pragma unroll
    for (int off = 16; off >= 1; off >>= 1)
        local += __shfl_xor_sync(0xffffffffu, local, off);
    if (tx == 0) red[ty] = local;
    __syncthreads();
    if (tid < 32) {
        float v = red[tid];
        #pragma unroll
        for (int off = 16; off >= 1; off >>= 1)
            v += __shfl_xor_sync(0xffffffffu, v, off);
        if (tid == 0)
            g_partial[(b * 8 + blockIdx.y) * 32 + blockIdx.x] = v;
    }
}

// Finalize: block 0 reduces loss; all blocks write indices-as-float tail.
__global__ __launch_bounds__(256) void vq_final(float* __restrict__ out, int total, int rows) {
    if (blockIdx.x == 0) {
        __shared__ double dred[256];
        double s = 0.0;
        for (int i = threadIdx.x; i < NPART; i += 256) s += (double)g_partial[i];
        dred[threadIdx.x] = s;
        __syncthreads();
        #pragma unroll
        for (int st = 128; st >= 1; st >>= 1) {
            if (threadIdx.x < st) dred[threadIdx.x] += dred[threadIdx.x + st];
            __syncthreads();
        }
        if (threadIdx.x == 0) {
            double loss = dred[0] / (double)total;
            out[total]     = (float)loss;
            out[total + 1] = (float)(0.25 * loss);
        }
    }
    int i = blockIdx.x * 256 + threadIdx.x;
    if (i < rows) out[total + 2 + i] = (float)g_idx[i];
}

// ---------------------------------------------------------------------------
extern "C" void kernel_launch(void* const* d_in, const int* in_sizes, int n_in,
                              void* d_out, int out_size)
{
    const float* z   = (const float*)d_in[0];   // [16,256,32,32]
    const float* emb = (const float*)d_in[1];   // [8192,256]
    float* out = (float*)d_out;
    const int z_total = in_sizes[0];            // 4194304
    const int rows = z_total / CDIM;            // 16384

    const int SM_TOTAL = 1024 + 3 * 128 * SA * 2;  // 203776 B
    cudaFuncSetAttribute(vq_gemm, cudaFuncAttributeMaxDynamicSharedMemorySize, SM_TOTAL);

    vq_prep_z<<<dim3(HW / 32, CDIM / 32, 16), dim3(32, 32)>>>(z);
    vq_prep_emb<<<512, 256>>>(emb);
    vq_rownorm<<<(rows + 127) / 128, 128>>>(z);
    vq_gemm<<<rows / TILE_M, 512, SM_TOTAL>>>(z, emb);
    vq_gather<<<dim3(HW / 32, CDIM / 32, 16), dim3(32, 32)>>>(z, emb, out);
    if (out_size >= z_total + 2 + rows)
        vq_final<<<(rows + 255) / 256, 256>>>(out, z_total, rows);
}

// round 13
// speedup vs baseline: 1.2604x; 1.2392x over previous
#include <cuda_runtime.h>
#include <cuda_bf16.h>
#include <math_constants.h>
#include <cstdint>

// ---------------- problem constants (fixed shapes) ----------------
#define CDIM   256
#define HW     1024
#define NROWS  16384
#define KCODES 8192
#define NPART  4096

// ---------------- GEMM tiling ----------------
#define TILE_M 128
#define TILE_N 128
#define NTILES (KCODES / TILE_N)   // 64
#define CAP    128                 // candidate list capacity per row
#define MARGIN 2.0e-4f             // shortlist margin (dot units)
#define SA     264                 // padded smem row stride in bf16 (528B)
#define SAB    (SA * 2)            // bytes

// ---------------- device scratch (no allocations allowed) ----------------
__device__ float          g_S[NROWS];
__device__ int            g_idx[NROWS];
__device__ float          g_partial[NPART];
__device__ int            g_cnt[NROWS];
__device__ int            g_cand[NROWS * CAP];
__device__ float          g_Zr[NROWS * CDIM];    // fp32 transposed z (row-major)
__device__ __nv_bfloat16  g_A[NROWS * CDIM];
__device__ __nv_bfloat16  g_B[KCODES * CDIM];

// ---------------- helpers ----------------
__device__ __forceinline__ uint32_t smem_u32(const void* p) {
    uint32_t a;
    asm("{ .reg .u64 t; cvta.to.shared.u64 t, %1; cvt.u32.u64 %0, t; }" : "=r"(a) : "l"(p));
    return a;
}
__device__ __forceinline__ void cp16(uint32_t dst, const void* src) {
    asm volatile("cp.async.cg.shared.global [%0], [%1], 16;" :: "r"(dst), "l"(src));
}
__device__ __forceinline__ void cp_commit() { asm volatile("cp.async.commit_group;" ::: "memory"); }
__device__ __forceinline__ void cp_wait0()  { asm volatile("cp.async.wait_group 0;" ::: "memory"); }

__device__ __forceinline__ void mma_bf16(float& c0, float& c1, float& c2, float& c3,
                                         uint32_t a0, uint32_t a1, uint32_t a2, uint32_t a3,
                                         uint32_t b0, uint32_t b1) {
    asm volatile("mma.sync.aligned.m16n8k16.row.col.f32.bf16.bf16.f32 "
                 "{%0,%1,%2,%3}, {%4,%5,%6,%7}, {%8,%9}, {%0,%1,%2,%3};"
                 : "+f"(c0), "+f"(c1), "+f"(c2), "+f"(c3)
                 : "r"(a0), "r"(a1), "r"(a2), "r"(a3), "r"(b0), "r"(b1));
}
__device__ __forceinline__ void ldsm4(uint32_t& r0, uint32_t& r1, uint32_t& r2, uint32_t& r3,
                                      uint32_t addr) {
    asm volatile("ldmatrix.sync.aligned.m8n8.x4.shared.b16 {%0,%1,%2,%3}, [%4];"
                 : "=r"(r0), "=r"(r1), "=r"(r2), "=r"(r3) : "r"(addr));
}
// float atomic max on shared (handles mixed signs)
__device__ __forceinline__ void atomicMaxFloatS(float* addr, float value) {
    if (value >= 0.f) atomicMax((int*)addr, __float_as_int(value));
    else              atomicMin((unsigned int*)addr, __float_as_uint(value));
}

// ---------------------------------------------------------------------------
// Prep: A[n][c] = bf16(z[b,c,hw]); Zr[n][c] = z[b,c,hw] (fp32); via transpose
// ---------------------------------------------------------------------------
__global__ __launch_bounds__(1024) void vq_prep_z(const float* __restrict__ z) {
    __shared__ float t[32][33];
    int hw0 = blockIdx.x * 32, c0 = blockIdx.y * 32, b = blockIdx.z;
    const float* zp = z + ((size_t)b * CDIM + c0) * HW + hw0;
    t[threadIdx.y][threadIdx.x] = zp[(size_t)threadIdx.y * HW + threadIdx.x];
    __syncthreads();
    float v = t[threadIdx.x][threadIdx.y];
    size_t o = (size_t)(b * HW + hw0 + threadIdx.y) * CDIM + c0 + threadIdx.x;
    g_A[o]  = __float2bfloat16(v);
    g_Zr[o] = v;
}
__global__ __launch_bounds__(256) void vq_prep_emb(const float* __restrict__ emb) {
    int t0 = blockIdx.x * 256 + threadIdx.x;
    for (int i = t0; i < KCODES * CDIM; i += gridDim.x * 256)
        g_B[i] = __float2bfloat16(emb[i]);
    if (t0 < NROWS) g_cnt[t0] = 0;
}

// ---------------------------------------------------------------------------
// S_n: sequential fp32 sum of z^2 in channel order (exact reference emulation)
// ---------------------------------------------------------------------------
__global__ __launch_bounds__(128) void vq_rownorm(const float* __restrict__ z) {
    int n = blockIdx.x * 128 + threadIdx.x;
    if (n >= NROWS) return;
    const float* p = z + (size_t)(n >> 10) * CDIM * HW + (n & (HW - 1));
    float s = 0.f;
    #pragma unroll 16
    for (int c = 0; c < CDIM; c++) {
        float v = p[(size_t)c * HW];
        s = __fadd_rn(s, __fmul_rn(v, v));
    }
    g_S[n] = s;
}

// ---------------------------------------------------------------------------
// bf16 HMMA GEMM + global-row-max margin shortlist. (R9 version, unchanged)
// 512 threads = 16 warps as 4(M) x 4(N); warp tile 32x32; block 128x128, K=256.
// ---------------------------------------------------------------------------
__global__ __launch_bounds__(512, 1) void vq_gemm(int dummy)
{
    extern __shared__ char smraw[];
    float* smax = (float*)smraw;                    // 128 floats (512B)
    __nv_bfloat16* Asm  = (__nv_bfloat16*)(smraw + 512);            // 128 x SA
    __nv_bfloat16* Bsm0 = (__nv_bfloat16*)(smraw + 512) + 128 * SA;
    __nv_bfloat16* Bsm1 = (__nv_bfloat16*)(smraw + 512) + 2 * 128 * SA;

    const int tid = threadIdx.x;
    const int wid = tid >> 5, lane = tid & 31;
    const int g = lane >> 2, t = lane & 3;
    const int wm = (wid >> 2) * 32;                 // warp row base
    const int wn = (wid & 3) * 32;                  // warp col base
    const int n0 = blockIdx.x * TILE_M;

    const uint32_t sA  = smem_u32(Asm);
    const uint32_t sB0 = smem_u32(Bsm0);
    const uint32_t sB1 = smem_u32(Bsm1);

    const uint32_t aLOff = (uint32_t)(((((lane >> 3) & 1) * 8) + (lane & 7)) * SAB + (lane >> 4) * 16);
    const uint32_t bLOff = (uint32_t)(((lane >> 4) * 8 + (lane & 7)) * SAB + ((lane >> 3) & 1) * 16);

    if (tid < 128) smax[tid] = -CUDART_INF_F;

    {
        const __nv_bfloat16* Ab = g_A + (size_t)n0 * CDIM;
        #pragma unroll
        for (int p = 0; p < 8; p++) {
            int i = tid + p * 512;
            int row = i >> 5, cc = i & 31;
            cp16(sA + row * SAB + cc * 16, Ab + (size_t)row * CDIM + cc * 8);
        }
        const __nv_bfloat16* Bb = g_B;
        #pragma unroll
        for (int p = 0; p < 8; p++) {
            int i = tid + p * 512;
            int row = i >> 5, cc = i & 31;
            cp16(sB0 + row * SAB + cc * 16, Bb + (size_t)row * CDIM + cc * 8);
        }
        cp_commit(); cp_wait0();
    }
    __syncthreads();

    int cur = 0;
    #pragma unroll 1
    for (int tt = 0; tt < NTILES; tt++) {
        if (tt + 1 < NTILES) {
            const __nv_bfloat16* Bb = g_B + (size_t)(tt + 1) * TILE_N * CDIM;
            uint32_t dst = cur ? sB0 : sB1;
            #pragma unroll
            for (int p = 0; p < 8; p++) {
                int i = tid + p * 512;
                int row = i >> 5, cc = i & 31;
                cp16(dst + row * SAB + cc * 16, Bb + (size_t)row * CDIM + cc * 8);
            }
        }
        cp_commit();

        const uint32_t sB = cur ? sB1 : sB0;

        float C[2][4][4];
        #pragma unroll
        for (int mf = 0; mf < 2; mf++)
            #pragma unroll
            for (int nf = 0; nf < 4; nf++)
                #pragma unroll
                for (int q = 0; q < 4; q++) C[mf][nf][q] = 0.f;

        uint32_t aF[2][2][4], bF[2][4][2];
        #pragma unroll
        for (int mf = 0; mf < 2; mf++)
            ldsm4(aF[0][mf][0], aF[0][mf][1], aF[0][mf][2], aF[0][mf][3],
                  sA + (wm + mf * 16) * SAB + aLOff);
        #pragma unroll
        for (int p = 0; p < 2; p++)
            ldsm4(bF[0][2 * p][0], bF[0][2 * p][1], bF[0][2 * p + 1][0], bF[0][2 * p + 1][1],
                  sB + (wn + p * 16) * SAB + bLOff);

        #pragma unroll
        for (int ks = 0; ks < 16; ks++) {
            const int cb = ks & 1;
            if (ks < 15) {
                const int nb = cb ^ 1;
                const uint32_t koff = (uint32_t)((ks + 1) * 32);
                #pragma unroll
                for (int mf = 0; mf < 2; mf++)
                    ldsm4(aF[nb][mf][0], aF[nb][mf][1], aF[nb][mf][2], aF[nb][mf][3],
                          sA + (wm + mf * 16) * SAB + koff + aLOff);
                #pragma unroll
                for (int p = 0; p < 2; p++)
                    ldsm4(bF[nb][2 * p][0], bF[nb][2 * p][1], bF[nb][2 * p + 1][0], bF[nb][2 * p + 1][1],
                          sB + (wn + p * 16) * SAB + koff + bLOff);
            }
            #pragma unroll
            for (int mf = 0; mf < 2; mf++)
                #pragma unroll
                for (int nf = 0; nf < 4; nf++)
                    mma_bf16(C[mf][nf][0], C[mf][nf][1], C[mf][nf][2], C[mf][nf][3],
                             aF[cb][mf][0], aF[cb][mf][1], aF[cb][mf][2], aF[cb][mf][3],
                             bF[cb][nf][0], bF[cb][nf][1]);
        }

        // epilogue phase 1: stripe max -> global row max
        #pragma unroll
        for (int mf = 0; mf < 2; mf++) {
            #pragma unroll
            for (int h = 0; h < 2; h++) {
                float lm = -CUDART_INF_F;
                #pragma unroll
                for (int nf = 0; nf < 4; nf++)
                    lm = fmaxf(lm, fmaxf(C[mf][nf][2 * h], C[mf][nf][2 * h + 1]));
                lm = fmaxf(lm, __shfl_xor_sync(0xffffffffu, lm, 1));
                lm = fmaxf(lm, __shfl_xor_sync(0xffffffffu, lm, 2));
                if (t == 0) atomicMaxFloatS(&smax[wm + mf * 16 + g + h * 8], lm);
            }
        }
        __syncthreads();
        // epilogue phase 2: append candidates vs global row threshold
        #pragma unroll
        for (int mf = 0; mf < 2; mf++) {
            #pragma unroll
            for (int h = 0; h < 2; h++) {
                const int rowl = wm + mf * 16 + g + h * 8;
                const float thr = smax[rowl] - MARGIN;
                const int rowg = n0 + rowl;
                #pragma unroll
                for (int nf = 0; nf < 4; nf++) {
                    #pragma unroll
                    for (int p = 0; p < 2; p++) {
                        float s = C[mf][nf][2 * h + p];
                        if (s >= thr) {
                            int col = tt * TILE_N + wn + nf * 8 + 2 * t + p;
                            int pos = atomicAdd(&g_cnt[rowg], 1);
                            if (pos < CAP) g_cand[rowg * CAP + pos] = col;
                        }
                    }
                }
            }
        }

        cp_wait0();
        __syncthreads();
        cur ^= 1;
    }
}

// ---------------------------------------------------------------------------
// Exact fp32 re-rank v3: one warp per row, lane = candidate slot.
// Loads via float4 from g_Zr (sequential) and emb (sequential); unpacked in
// ascending-c order -> fma chain bit-identical to the R3-passing recurrence.
// ---------------------------------------------------------------------------
__global__ __launch_bounds__(256) void vq_rerank(const float* __restrict__ emb)
{
    const int w = threadIdx.x >> 5, lane = threadIdx.x & 31;
    const int n = blockIdx.x * 8 + w;
    if (n >= NROWS) return;
    const float4* zr4 = (const float4*)(g_Zr + (size_t)n * CDIM);
    const float S = g_S[n];
    const int cnt = g_cnt[n];

    float bestd = CUDART_INF_F;
    int   besti = 0x7fffffff;

    if (cnt <= CAP) {
        for (int base = 0; base < cnt; base += 32) {
            int q = base + lane;
            float d = CUDART_INF_F; int k = 0x7fffffff;
            if (q < cnt) {
                k = g_cand[n * CAP + q];
                const float4* ep4 = (const float4*)(emb + (size_t)k * CDIM);
                float acc = 0.f;
                #pragma unroll 8
                for (int i = 0; i < CDIM / 4; i++) {
                    float4 a = zr4[i], b = ep4[i];
                    acc = fmaf(a.x, b.x, acc);
                    acc = fmaf(a.y, b.y, acc);
                    acc = fmaf(a.z, b.z, acc);
                    acc = fmaf(a.w, b.w, acc);
                }
                d = __fadd_rn(S, -2.0f * acc);
            }
            if (d < bestd || (d == bestd && k < besti)) { bestd = d; besti = k; }
        }
    } else {
        // correctness net (unreachable with global-row-max threshold)
        for (int k = lane; k < KCODES; k += 32) {
            const float4* ep4 = (const float4*)(emb + (size_t)k * CDIM);
            float acc = 0.f;
            #pragma unroll 8
            for (int i = 0; i < CDIM / 4; i++) {
                float4 a = zr4[i], b = ep4[i];
                acc = fmaf(a.x, b.x, acc);
                acc = fmaf(a.y, b.y, acc);
                acc = fmaf(a.z, b.z, acc);
                acc = fmaf(a.w, b.w, acc);
            }
            float d = __fadd_rn(S, -2.0f * acc);
            if (d < bestd || (d == bestd && k < besti)) { bestd = d; besti = k; }
        }
    }
    #pragma unroll
    for (int off = 16; off >= 1; off >>= 1) {
        float od = __shfl_xor_sync(0xffffffffu, bestd, off);
        int   oi = __shfl_xor_sync(0xffffffffu, besti, off);
        if (od < bestd || (od == bestd && oi < besti)) { bestd = od; besti = oi; }
    }
    if (lane == 0) g_idx[n] = besti;
}

// ---------------------------------------------------------------------------
// Coalesced gather: 32x32 (hw x c) patches via smem transpose.
// Rounding identical to reference: d = fl(q - z); out = fl(z + d).
// ---------------------------------------------------------------------------
__global__ __launch_bounds__(1024) void vq_gather(
    const float* __restrict__ z, const float* __restrict__ emb,
    float* __restrict__ out)
{
    __shared__ float eT[32][33];
    __shared__ int   ids[32];
    __shared__ float red[32];

    const int tx = threadIdx.x, ty = threadIdx.y;
    const int tid = ty * 32 + tx;
    const int hw0 = blockIdx.x * 32, c0 = blockIdx.y * 32, b = blockIdx.z;

    if (tid < 32) ids[tid] = g_idx[b * HW + hw0 + tid];
    __syncthreads();

    eT[ty][tx] = emb[(size_t)ids[ty] * CDIM + c0 + tx];
    __syncthreads();

    const size_t e = (size_t)b * (CDIM * HW) + (size_t)(c0 + ty) * HW + hw0 + tx;
    float zv = z[e];
    float q  = eT[tx][ty];
    float d  = __fadd_rn(q, -zv);
    out[e] = __fadd_rn(zv, d);
    float local = d * d;

    #pragma unroll
    for (int off = 16; off >= 1; off >>= 1)
        local += __shfl_xor_sync(0xffffffffu, local, off);
    if (tx == 0) red[ty] = local;
    __syncthreads();
    if (tid < 32) {
        float v = red[tid];
        #pragma unroll
        for (int off = 16; off >= 1; off >>= 1)
            v += __shfl_xor_sync(0xffffffffu, v, off);
        if (tid == 0)
            g_partial[(b * 8 + blockIdx.y) * 32 + blockIdx.x] = v;
    }
}

// Finalize: block 0 reduces loss; all blocks write indices-as-float tail.
__global__ __launch_bounds__(256) void vq_final(float* __restrict__ out, int total, int rows) {
    if (blockIdx.x == 0) {
        __shared__ double dred[256];
        double s = 0.0;
        for (int i = threadIdx.x; i < NPART; i += 256) s += (double)g_partial[i];
        dred[threadIdx.x] = s;
        __syncthreads();
        #pragma unroll
        for (int st = 128; st >= 1; st >>= 1) {
            if (threadIdx.x < st) dred[threadIdx.x] += dred[threadIdx.x + st];
            __syncthreads();
        }
        if (threadIdx.x == 0) {
            double loss = dred[0] / (double)total;
            out[total]     = (float)loss;
            out[total + 1] = (float)(0.25 * loss);
        }
    }
    int i = blockIdx.x * 256 + threadIdx.x;
    if (i < rows) out[total + 2 + i] = (float)g_idx[i];
}

// ---------------------------------------------------------------------------
extern "C" void kernel_launch(void* const* d_in, const int* in_sizes, int n_in,
                              void* d_out, int out_size)
{
    const float* z   = (const float*)d_in[0];   // [16,256,32,32]
    const float* emb = (const float*)d_in[1];   // [8192,256]
    float* out = (float*)d_out;
    const int z_total = in_sizes[0];            // 4194304
    const int rows = z_total / CDIM;            // 16384

    const int SM_TOTAL = 512 + 3 * 128 * SA * 2;  // 203264 B
    cudaFuncSetAttribute(vq_gemm, cudaFuncAttributeMaxDynamicSharedMemorySize, SM_TOTAL);

    vq_prep_z<<<dim3(HW / 32, CDIM / 32, 16), dim3(32, 32)>>>(z);
    vq_prep_emb<<<512, 256>>>(emb);
    vq_rownorm<<<(rows + 127) / 128, 128>>>(z);
    vq_gemm<<<rows / TILE_M, 512, SM_TOTAL>>>(0);
    vq_rerank<<<(rows + 7) / 8, 256>>>(emb);
    vq_gather<<<dim3(HW / 32, CDIM / 32, 16), dim3(32, 32)>>>(z, emb, out);
    if (out_size >= z_total + 2 + rows)
        vq_final<<<(rows + 255) / 256, 256>>>(out, z_total, rows);
}